// round 2
// baseline (speedup 1.0000x reference)
#include <cuda_runtime.h>

typedef unsigned long long ull;

#define NTOT   262144           // B*C
#define SCALE  0.14433756729740643f   // 1/sqrt(48)
#define WT_ROWS 128
#define WT_STRIDE 58             // floats per row (even -> LDS.64 aligned, 2-phase conflict-free)

// Folded weights: WT[col][d] ; col<55: M column (scale folded), 55..109: G column, rest zero.
__device__ float g_WT[WT_ROWS * WT_STRIDE];

__global__ void prep_kernel(const float* __restrict__ wq, const float* __restrict__ wk,
                            const float* __restrict__ wv, const float* __restrict__ wfc) {
    int idx = blockIdx.x * blockDim.x + threadIdx.x;
    if (idx >= WT_ROWS * WT_STRIDE) return;
    int col = idx / WT_STRIDE;
    int d   = idx - col * WT_STRIDE;
    float val = 0.f;
    if (d < 55 && col < 110) {
        if (col < 55) {
            // M[d][col] = SCALE * sum_e wq[e,d]*wk[e,col]
            float s = 0.f;
            #pragma unroll 8
            for (int e = 0; e < 48; e++) s += wq[e * 55 + d] * wk[e * 55 + col];
            val = s * SCALE;
        } else {
            // G[d][dd] = sum_e wv[e,d]*wfc[dd,e]
            int dd = col - 55;
            float s = 0.f;
            #pragma unroll 8
            for (int e = 0; e < 48; e++) s += wv[e * 55 + d] * wfc[dd * 48 + e];
            val = s;
        }
    }
    g_WT[idx] = val;
}

// ---- packed f32x2 helpers ----
__device__ __forceinline__ void fma2(ull& d, ull a, ull b) {
    asm("fma.rn.f32x2 %0, %1, %2, %0;" : "+l"(d) : "l"(a), "l"(b));
}
__device__ __forceinline__ void unpk(ull v, float& lo, float& hi) {
    asm("mov.b64 {%0,%1}, %2;" : "=f"(lo), "=f"(hi) : "l"(v));
}

// scatter one x element from linear patch layout into (s,d) layout
__device__ __forceinline__ void scat(float* xs, int l, float v) {
    int r  = l / 10;          // row in 22x10 patch block
    int cc = l - r * 10;
    int p1 = r / 11, h = r - p1 * 11;
    int p2 = cc / 5, w = cc - p2 * 5;
    int s = p1 * 2 + p2;
    int d = h * 5 + w;
    xs[s * 56 + d] = v;
}

__global__ __launch_bounds__(256) void mha_kernel(const float* __restrict__ x,
                                                  const float* __restrict__ bfc,
                                                  float* __restrict__ out) {
    __shared__ __align__(16) float sWT[WT_ROWS * WT_STRIDE];
    __shared__ __align__(16) float sB[56];
    __shared__ __align__(16) float sX[8][4 * 56];   // per-warp x, (s,d) layout, d padded w/ zeros
    __shared__ __align__(16) float sT[8][4 * 56];   // per-warp T (then reused as output stage)
    __shared__ __align__(16) float sA[8][16];       // per-warp attn

    for (int i = threadIdx.x; i < WT_ROWS * WT_STRIDE; i += 256) sWT[i] = g_WT[i];
    for (int i = threadIdx.x; i < 56; i += 256) sB[i] = (i < 55) ? bfc[i] : 0.f;
    __syncthreads();

    const int w    = threadIdx.x >> 5;
    const int lane = threadIdx.x & 31;
    float* xs = sX[w];
    float* ts = sT[w];
    float* as = sA[w];

    const int c0 = lane, c1 = lane + 32, c2 = lane + 64, c3 = lane + 96;
    const float* w0p = sWT + c0 * WT_STRIDE;
    const float* w1p = sWT + c1 * WT_STRIDE;
    const float* w2p = sWT + c2 * WT_STRIDE;
    const float* w3p = sWT + c3 * WT_STRIDE;

    const int gw = blockIdx.x * 8 + w;
    const int nw = gridDim.x * 8;

    for (int n = gw; n < NTOT; n += nw) {
        // ---- load x (880B contiguous) and scatter to (s,d) layout ----
        const float4* xin = (const float4*)(x + (size_t)n * 220);
        {
            float4 v = xin[lane];
            int l = lane * 4;
            scat(xs, l + 0, v.x); scat(xs, l + 1, v.y);
            scat(xs, l + 2, v.z); scat(xs, l + 3, v.w);
            if (lane < 23) {
                float4 v2 = xin[32 + lane];
                int l2 = (32 + lane) * 4;
                scat(xs, l2 + 0, v2.x); scat(xs, l2 + 1, v2.y);
                scat(xs, l2 + 2, v2.z); scat(xs, l2 + 3, v2.w);
            }
            if (lane < 4) xs[lane * 56 + 55] = 0.f;   // pad d=55
        }
        __syncwarp();

        // ---- main GEMM: [T|U][s][col] = sum_d x[s][d] * WT[col][d]  (packed f32x2) ----
        ull acc[4][4];
        #pragma unroll
        for (int s = 0; s < 4; s++)
            #pragma unroll
            for (int c = 0; c < 4; c++) acc[s][c] = 0ull;

        #pragma unroll 4
        for (int d = 0; d < 56; d += 2) {
            ull xv0 = *(const ull*)(xs +   0 + d);
            ull xv1 = *(const ull*)(xs +  56 + d);
            ull xv2 = *(const ull*)(xs + 112 + d);
            ull xv3 = *(const ull*)(xs + 168 + d);
            ull wv0 = *(const ull*)(w0p + d);
            ull wv1 = *(const ull*)(w1p + d);
            ull wv2 = *(const ull*)(w2p + d);
            ull wv3 = *(const ull*)(w3p + d);
            fma2(acc[0][0], xv0, wv0); fma2(acc[1][0], xv1, wv0);
            fma2(acc[2][0], xv2, wv0); fma2(acc[3][0], xv3, wv0);
            fma2(acc[0][1], xv0, wv1); fma2(acc[1][1], xv1, wv1);
            fma2(acc[2][1], xv2, wv1); fma2(acc[3][1], xv3, wv1);
            fma2(acc[0][2], xv0, wv2); fma2(acc[1][2], xv1, wv2);
            fma2(acc[2][2], xv2, wv2); fma2(acc[3][2], xv3, wv2);
            fma2(acc[0][3], xv0, wv3); fma2(acc[1][3], xv1, wv3);
            fma2(acc[2][3], xv2, wv3); fma2(acc[3][3], xv3, wv3);
        }

        float Tv[4][4];
        #pragma unroll
        for (int s = 0; s < 4; s++)
            #pragma unroll
            for (int c = 0; c < 4; c++) {
                float lo, hi; unpk(acc[s][c], lo, hi);
                Tv[s][c] = lo + hi;
            }

        // ---- store T columns (cols < 55) to smem ----
        #pragma unroll
        for (int s = 0; s < 4; s++) ts[s * 56 + c0] = Tv[s][0];
        if (lane < 23) {
            #pragma unroll
            for (int s = 0; s < 4; s++) ts[s * 56 + c1] = Tv[s][1];
        }
        if (lane == 0) {
            #pragma unroll
            for (int s = 0; s < 4; s++) ts[s * 56 + 55] = 0.f;
        }
        __syncwarp();

        // ---- S = T x^T (4x4), softmax: lanes 0..15 own (s,t); lanes 16..31 compute a
        //      harmless duplicate (s,t from lane&15) so every address stays in-bounds ----
        {
            int s = (lane >> 2) & 3, t = lane & 3;
            const float4* tr = (const float4*)(ts + s * 56);
            const float4* xr = (const float4*)(xs + t * 56);
            float sv = 0.f;
            #pragma unroll
            for (int i = 0; i < 14; i++) {
                float4 a = tr[i], b = xr[i];
                sv += a.x * b.x + a.y * b.y + a.z * b.z + a.w * b.w;
            }
            float m = sv;
            m = fmaxf(m, __shfl_xor_sync(0xffffffffu, m, 1));
            m = fmaxf(m, __shfl_xor_sync(0xffffffffu, m, 2));
            float e = __expf(sv - m);
            float sm = e;
            sm += __shfl_xor_sync(0xffffffffu, sm, 1);
            sm += __shfl_xor_sync(0xffffffffu, sm, 2);
            float p = e / sm;
            if (lane < 16) as[lane] = p;
        }
        __syncwarp();

        float att[16];
        #pragma unroll
        for (int i = 0; i < 16; i++) att[i] = as[i];
        __syncwarp();   // everyone has read as + done reading ts for S; ts reused below

        // ---- out[s][dcol] = b[dcol] + sum_t att[s][t] * U[t][dcol]; stage in ts (linear layout) ----
        // U columns owned by this lane: c1 (if lane>=23), c2 (always), c3 (if lane<14)
        if (lane >= 23) {
            int dcol = c1 - 55;
            int h = dcol / 5, ww = dcol - h * 5;
            float b = sB[dcol];
            #pragma unroll
            for (int s = 0; s < 4; s++) {
                float o = b + att[s * 4 + 0] * Tv[0][1] + att[s * 4 + 1] * Tv[1][1]
                            + att[s * 4 + 2] * Tv[2][1] + att[s * 4 + 3] * Tv[3][1];
                int l = ((s >> 1) * 11 + h) * 10 + (s & 1) * 5 + ww;
                ts[l] = o;
            }
        }
        {
            int dcol = c2 - 55;
            int h = dcol / 5, ww = dcol - h * 5;
            float b = sB[dcol];
            #pragma unroll
            for (int s = 0; s < 4; s++) {
                float o = b + att[s * 4 + 0] * Tv[0][2] + att[s * 4 + 1] * Tv[1][2]
                            + att[s * 4 + 2] * Tv[2][2] + att[s * 4 + 3] * Tv[3][2];
                int l = ((s >> 1) * 11 + h) * 10 + (s & 1) * 5 + ww;
                ts[l] = o;
            }
        }
        if (lane < 14) {
            int dcol = c3 - 55;
            int h = dcol / 5, ww = dcol - h * 5;
            float b = sB[dcol];
            #pragma unroll
            for (int s = 0; s < 4; s++) {
                float o = b + att[s * 4 + 0] * Tv[0][3] + att[s * 4 + 1] * Tv[1][3]
                            + att[s * 4 + 2] * Tv[2][3] + att[s * 4 + 3] * Tv[3][3];
                int l = ((s >> 1) * 11 + h) * 10 + (s & 1) * 5 + ww;
                ts[l] = o;
            }
        }
        __syncwarp();

        // ---- coalesced write: 220 contiguous floats as float4 ----
        float4* op = (float4*)(out + (size_t)n * 220);
        op[lane] = ((const float4*)ts)[lane];
        if (lane < 23) op[32 + lane] = ((const float4*)ts)[32 + lane];
        __syncwarp();   // ts/xs reused next iteration
    }
}

extern "C" void kernel_launch(void* const* d_in, const int* in_sizes, int n_in,
                              void* d_out, int out_size) {
    const float* x   = (const float*)d_in[0];
    const float* wq  = (const float*)d_in[1];
    const float* wk  = (const float*)d_in[2];
    const float* wv  = (const float*)d_in[3];
    const float* wfc = (const float*)d_in[4];
    const float* bfc = (const float*)d_in[5];
    float* out = (float*)d_out;

    prep_kernel<<<(WT_ROWS * WT_STRIDE + 255) / 256, 256>>>(wq, wk, wv, wfc);
    mha_kernel<<<592, 256>>>(x, bfc, out);
}

// round 3
// speedup vs baseline: 1.1876x; 1.1876x over previous
#include <cuda_runtime.h>

typedef unsigned long long ull;

#define NTOT      262144                  // B*C
#define SCALE     0.14433756729740643f    // 1/sqrt(48)
#define WT_ROWS   128
#define WT_STRIDE 60                      // floats/row: 240B, 16B-aligned, conflict-free LDS.128

// Folded weights: WT[col][d]; col<55: M column (scale folded), 55..109: G column, rest zero.
__device__ float g_WT[WT_ROWS * WT_STRIDE];

__global__ void prep_kernel(const float* __restrict__ wq, const float* __restrict__ wk,
                            const float* __restrict__ wv, const float* __restrict__ wfc) {
    int idx = blockIdx.x * blockDim.x + threadIdx.x;
    if (idx >= WT_ROWS * WT_STRIDE) return;
    int col = idx / WT_STRIDE;
    int d   = idx - col * WT_STRIDE;
    float val = 0.f;
    if (d < 55 && col < 110) {
        if (col < 55) {
            float s = 0.f;
            #pragma unroll 8
            for (int e = 0; e < 48; e++) s += wq[e * 55 + d] * wk[e * 55 + col];
            val = s * SCALE;
        } else {
            int dd = col - 55;
            float s = 0.f;
            #pragma unroll 8
            for (int e = 0; e < 48; e++) s += wv[e * 55 + d] * wfc[dd * 48 + e];
            val = s;
        }
    }
    g_WT[idx] = val;
}

// ---- packed f32x2 helpers ----
__device__ __forceinline__ void fma2(ull& d, ull a, ull b) {
    asm("fma.rn.f32x2 %0, %1, %2, %0;" : "+l"(d) : "l"(a), "l"(b));
}
__device__ __forceinline__ void unpk(ull v, float& lo, float& hi) {
    asm("mov.b64 {%0,%1}, %2;" : "=f"(lo), "=f"(hi) : "l"(v));
}

// scatter one x element from linear patch layout (within one n) into (s,d) layout
__device__ __forceinline__ void scat(float* xs, int l, float v) {
    int r  = l / 10;
    int cc = l - r * 10;
    int p1 = r / 11, h = r - p1 * 11;
    int p2 = cc / 5, w = cc - p2 * 5;
    xs[(p1 * 2 + p2) * 56 + h * 5 + w] = v;
}

__global__ __launch_bounds__(128, 3) void mha_kernel(const float* __restrict__ x,
                                                     const float* __restrict__ bfc,
                                                     float* __restrict__ out) {
    __shared__ __align__(16) float sWT[WT_ROWS * WT_STRIDE];   // 30720 B
    __shared__ __align__(16) float sB[56];
    __shared__ __align__(16) float sX[4][2][224];              // [warp][j][s*56+d]
    __shared__ __align__(16) float sT[4][2][224];              // T, then output staging
    __shared__ __align__(16) float sA[4][32];                  // attn: [0..15]=n0, [16..31]=n1

    for (int i = threadIdx.x; i < WT_ROWS * WT_STRIDE; i += 128) sWT[i] = g_WT[i];
    for (int i = threadIdx.x; i < 56; i += 128) sB[i] = (i < 55) ? bfc[i] : 0.f;
    __syncthreads();

    const int w    = threadIdx.x >> 5;
    const int lane = threadIdx.x & 31;
    float* xs0 = sX[w][0]; float* xs1 = sX[w][1];
    float* ts0 = sT[w][0]; float* ts1 = sT[w][1];
    float* as  = sA[w];

    const int c0 = lane, c1 = lane + 32, c2 = lane + 64, c3 = lane + 96;
    const float* w0p = sWT + c0 * WT_STRIDE;
    const float* w1p = sWT + c1 * WT_STRIDE;
    const float* w2p = sWT + c2 * WT_STRIDE;
    const float* w3p = sWT + c3 * WT_STRIDE;

    // hoisted epilogue constants (per owned U column)
    const int  d1 = c1 - 55, d2 = c2 - 55, d3 = c3 - 55;        // d1 valid if lane>=23, d3 if lane<14
    const int  b1i = (lane >= 23) ? d1 : 0;
    const int  b3i = (lane < 14) ? d3 : 0;
    const float bia1 = sB[b1i], bia2 = sB[d2], bia3 = sB[b3i];
    const int  l1 = (b1i / 5) * 10 + (b1i % 5);                 // h*10+w base
    const int  l2 = (d2  / 5) * 10 + (d2  % 5);
    const int  l3 = (b3i / 5) * 10 + (b3i % 5);

    const int gw = blockIdx.x * 4 + w;
    const int nw = gridDim.x * 4;

    for (int p = gw; p < NTOT / 2; p += nw) {
        const size_t n0 = (size_t)p * 2;

        // ---- load x for both n (440 contiguous floats = 110 float4), scatter to (s,d) ----
        const float4* xin = (const float4*)(x + n0 * 220);
        #pragma unroll
        for (int r = 0; r < 4; r++) {
            int idx = lane + 32 * r;
            if (idx < 110) {
                float4 v = xin[idx];
                float* xsj = (idx < 55) ? xs0 : xs1;
                int l = idx * 4 - ((idx < 55) ? 0 : 220);
                scat(xsj, l + 0, v.x); scat(xsj, l + 1, v.y);
                scat(xsj, l + 2, v.z); scat(xsj, l + 3, v.w);
            }
        }
        if (lane < 8) { float* b = (lane < 4) ? xs0 : xs1; b[(lane & 3) * 56 + 55] = 0.f; }
        __syncwarp();

        // ---- GEMM: [T|U]_j[s][col] = sum_d x_j[s][d] * WT[col][d], 8 rows x 4 cols ----
        ull acc[8][4];
        #pragma unroll
        for (int r = 0; r < 8; r++)
            #pragma unroll
            for (int c = 0; c < 4; c++) acc[r][c] = 0ull;

        #pragma unroll 2
        for (int dd = 0; dd < 56; dd += 4) {
            ulonglong2 wv0 = *(const ulonglong2*)(w0p + dd);
            ulonglong2 wv1 = *(const ulonglong2*)(w1p + dd);
            ulonglong2 wv2 = *(const ulonglong2*)(w2p + dd);
            ulonglong2 wv3 = *(const ulonglong2*)(w3p + dd);
            ulonglong2 xv[8];
            #pragma unroll
            for (int r = 0; r < 8; r++)
                xv[r] = *(const ulonglong2*)(((r < 4) ? xs0 : xs1) + (r & 3) * 56 + dd);
            #pragma unroll
            for (int r = 0; r < 8; r++) {
                fma2(acc[r][0], xv[r].x, wv0.x); fma2(acc[r][0], xv[r].y, wv0.y);
                fma2(acc[r][1], xv[r].x, wv1.x); fma2(acc[r][1], xv[r].y, wv1.y);
                fma2(acc[r][2], xv[r].x, wv2.x); fma2(acc[r][2], xv[r].y, wv2.y);
                fma2(acc[r][3], xv[r].x, wv3.x); fma2(acc[r][3], xv[r].y, wv3.y);
            }
        }

        float Tv[8][4];
        #pragma unroll
        for (int r = 0; r < 8; r++)
            #pragma unroll
            for (int c = 0; c < 4; c++) {
                float lo, hi; unpk(acc[r][c], lo, hi);
                Tv[r][c] = lo + hi;
            }

        // ---- store T columns (cols < 55) for both j ----
        #pragma unroll
        for (int s = 0; s < 4; s++) { ts0[s * 56 + c0] = Tv[s][0]; ts1[s * 56 + c0] = Tv[4 + s][0]; }
        if (lane < 23) {
            #pragma unroll
            for (int s = 0; s < 4; s++) { ts0[s * 56 + c1] = Tv[s][1]; ts1[s * 56 + c1] = Tv[4 + s][1]; }
        }
        if (lane == 0) {
            #pragma unroll
            for (int s = 0; s < 4; s++) { ts0[s * 56 + 55] = 0.f; ts1[s * 56 + 55] = 0.f; }
        }
        __syncwarp();

        // ---- S = T x^T (4x4) + softmax; lanes 0..15 -> n0, lanes 16..31 -> n1 ----
        {
            int q = lane & 15;
            int s = q >> 2, t = q & 3;
            const float* tsj = (lane < 16) ? ts0 : ts1;
            const float* xsj = (lane < 16) ? xs0 : xs1;
            const float4* tr = (const float4*)(tsj + s * 56);
            const float4* xr = (const float4*)(xsj + t * 56);
            float sv = 0.f;
            #pragma unroll
            for (int i = 0; i < 14; i++) {
                float4 a = tr[i], b = xr[i];
                sv += a.x * b.x + a.y * b.y + a.z * b.z + a.w * b.w;
            }
            float m = sv;
            m = fmaxf(m, __shfl_xor_sync(0xffffffffu, m, 1));
            m = fmaxf(m, __shfl_xor_sync(0xffffffffu, m, 2));
            float e = __expf(sv - m);
            float sm = e;
            sm += __shfl_xor_sync(0xffffffffu, sm, 1);
            sm += __shfl_xor_sync(0xffffffffu, sm, 2);
            as[lane] = e / sm;
        }
        __syncwarp();

        // ---- epilogue per j: out = b + att * U, stage linear, write coalesced ----
        #pragma unroll
        for (int j = 0; j < 2; j++) {
            float* tsj = j ? ts1 : ts0;
            float att[16];
            #pragma unroll
            for (int i = 0; i < 16; i++) att[i] = as[j * 16 + i];
            const int jb = j * 4;

            if (lane >= 23) {
                #pragma unroll
                for (int s = 0; s < 4; s++) {
                    float o = bia1 + att[s*4+0]*Tv[jb+0][1] + att[s*4+1]*Tv[jb+1][1]
                                   + att[s*4+2]*Tv[jb+2][1] + att[s*4+3]*Tv[jb+3][1];
                    tsj[l1 + (s >> 1) * 110 + (s & 1) * 5] = o;
                }
            }
            {
                #pragma unroll
                for (int s = 0; s < 4; s++) {
                    float o = bia2 + att[s*4+0]*Tv[jb+0][2] + att[s*4+1]*Tv[jb+1][2]
                                   + att[s*4+2]*Tv[jb+2][2] + att[s*4+3]*Tv[jb+3][2];
                    tsj[l2 + (s >> 1) * 110 + (s & 1) * 5] = o;
                }
            }
            if (lane < 14) {
                #pragma unroll
                for (int s = 0; s < 4; s++) {
                    float o = bia3 + att[s*4+0]*Tv[jb+0][3] + att[s*4+1]*Tv[jb+1][3]
                                   + att[s*4+2]*Tv[jb+2][3] + att[s*4+3]*Tv[jb+3][3];
                    tsj[l3 + (s >> 1) * 110 + (s & 1) * 5] = o;
                }
            }
            __syncwarp();

            float4* op = (float4*)(out + (n0 + j) * 220);
            op[lane] = ((const float4*)tsj)[lane];
            if (lane < 23) op[32 + lane] = ((const float4*)tsj)[32 + lane];
        }
        __syncwarp();   // ts/xs reused next iteration
    }
}

extern "C" void kernel_launch(void* const* d_in, const int* in_sizes, int n_in,
                              void* d_out, int out_size) {
    const float* x   = (const float*)d_in[0];
    const float* wq  = (const float*)d_in[1];
    const float* wk  = (const float*)d_in[2];
    const float* wv  = (const float*)d_in[3];
    const float* wfc = (const float*)d_in[4];
    const float* bfc = (const float*)d_in[5];
    float* out = (float*)d_out;

    prep_kernel<<<(WT_ROWS * WT_STRIDE + 255) / 256, 256>>>(wq, wk, wv, wfc);
    mha_kernel<<<444, 128>>>(x, bfc, out);
}

// round 5
// speedup vs baseline: 1.4507x; 1.2215x over previous
#include <cuda_runtime.h>
#include <cuda_fp16.h>
#include <cstdint>

#define NTOT   262144
#define NTILES 8192                     // NTOT / 32 n per tile
#define SCALE  0.14433756729740643f     // 1/sqrt(48)

// ---- smem layout (bytes, from 1KB-aligned base) ----
// A: 128 rows x 136 fp16 (pitch 272B). k: [0..54]=xh, 55=0, [56..110]=xl, 111..135=0
#define OFF_A   0
// B: 112 rows(j) x 184 fp16 (pitch 368B). k: [0..55]=wh, [56..111]=wh, [112..167]=wl, 168+=0
#define OFF_B   34816
// XP: x fp32 copy, 128 rows x 60 f32 (pitch 240B), pads zero
#define OFF_XP  76032
// DS: D staging, 128 rows x 116 f32 (pitch 464B)
#define OFF_DS  106752
// OS: out staging, 32 n x 224 f32
#define OFF_OS  166144
// AT: attn, 32 n x 4 s x float4
#define OFF_AT  194816
// SB: bias, 64 f32 (55 real + zeros)
#define OFF_SB  196864
#define SMEM_USED 197120
#define SMEM_TOTAL (SMEM_USED + 1024)

// precomputed folded B in fp16 (same layout as smem B)
__device__ unsigned short g_B[112 * 184];

// ============ prep: fold weights, fp16 hi/lo split ============
__global__ void prep_kernel(const float* __restrict__ wq, const float* __restrict__ wk,
                            const float* __restrict__ wv, const float* __restrict__ wfc) {
    int idx = blockIdx.x * blockDim.x + threadIdx.x;
    if (idx >= 112 * 184) return;
    int j = idx / 184;
    int k = idx - j * 184;
    int sec = (k < 56) ? 0 : (k < 112) ? 1 : (k < 168) ? 2 : 3;
    float w = 0.f;
    if (sec < 3) {
        int d = k - sec * 56;
        if (d < 55) {
            if (j < 55) {                         // M[d][j] = SCALE * wq(:,d).wk(:,j)
                float s = 0.f;
                #pragma unroll 8
                for (int e = 0; e < 48; e++) s += wq[e * 55 + d] * wk[e * 55 + j];
                w = s * SCALE;
            } else if (j >= 56 && j < 111) {      // G[d][dd] = wv(:,d).wfc(dd,:)
                int dd = j - 56;
                float s = 0.f;
                #pragma unroll 8
                for (int e = 0; e < 48; e++) s += wv[e * 55 + d] * wfc[dd * 48 + e];
                w = s;
            }
        }
    }
    __half wh = __float2half_rn(w);
    __half o;
    if (sec == 2)      o = __float2half_rn(w - __half2float(wh));   // wl
    else if (sec == 3) o = __float2half_rn(0.f);
    else               o = wh;
    g_B[idx] = __half_as_ushort(o);
}

// ============ PTX helpers (baseline ISA only) ============
__device__ __forceinline__ uint32_t s2u(const void* p) {
    uint32_t a;
    asm("{ .reg .u64 t; cvta.to.shared.u64 t, %1; cvt.u32.u64 %0, t; }" : "=r"(a) : "l"(p));
    return a;
}
__device__ __forceinline__ void ldsm4(uint32_t* r, uint32_t addr) {
    asm volatile("ldmatrix.sync.aligned.m8n8.x4.shared.b16 {%0,%1,%2,%3}, [%4];"
                 : "=r"(r[0]), "=r"(r[1]), "=r"(r[2]), "=r"(r[3]) : "r"(addr));
}
__device__ __forceinline__ void mma16816(float* c, const uint32_t* a, uint32_t b0, uint32_t b1) {
    asm volatile("mma.sync.aligned.m16n8k16.row.col.f32.f16.f16.f32 "
                 "{%0,%1,%2,%3}, {%4,%5,%6,%7}, {%8,%9}, {%0,%1,%2,%3};"
                 : "+f"(c[0]), "+f"(c[1]), "+f"(c[2]), "+f"(c[3])
                 : "r"(a[0]), "r"(a[1]), "r"(a[2]), "r"(a[3]), "r"(b0), "r"(b1));
}

// ============ main kernel ============
__global__ __launch_bounds__(256) void mha_kernel(const float* __restrict__ x,
                                                  const float* __restrict__ bfc,
                                                  float* __restrict__ out) {
    extern __shared__ char smraw[];
    uint32_t sb0 = s2u(smraw);
    uint32_t sb  = (sb0 + 1023u) & ~1023u;
    char* sm = smraw + (sb - sb0);

    const int tid  = threadIdx.x;
    const int wid  = tid >> 5;
    const int lane = tid & 31;

    // ---- one-time init ----
    for (int i = tid; i < 112 * 184; i += 256)
        ((unsigned short*)(sm + OFF_B))[i] = g_B[i];
    for (int i = tid; i < 34816 / 4; i += 256)           // zero A (pads persist)
        *(uint32_t*)(sm + OFF_A + i * 4) = 0u;
    for (int i = tid; i < 30720 / 4; i += 256)           // zero XP (pads persist)
        *(float*)(sm + OFF_XP + i * 4) = 0.f;
    for (int i = tid; i < 64; i += 256)
        *(float*)(sm + OFF_SB + i * 4) = (i < 55) ? bfc[i] : 0.f;
    __syncthreads();

    // ldmatrix per-lane address components
    const int R0 = wid * 16;
    const uint32_t aAddrBase = sb + OFF_A + (uint32_t)(R0 + (lane & 15)) * 272
                             + (uint32_t)((lane >> 4) & 1) * 16;
    const int jb   = (lane & 7) + ((lane >> 4) & 1) * 8;
    const int kadd = ((lane >> 3) & 1) * 16;

    float* DS = (float*)(sm + OFF_DS);
    const float* XP = (const float*)(sm + OFF_XP);
    const float* SB = (const float*)(sm + OFF_SB);

    for (int t = blockIdx.x; t < NTILES; t += gridDim.x) {
        // ======== Stage A: load x tile, fp16 split, scatter ========
        {
            const float4* xin = (const float4*)(x + (size_t)t * 7040);
            #pragma unroll
            for (int i = 0; i < 7; i++) {
                int idx = tid + 256 * i;
                if (idx < 1760) {
                    float4 v = xin[idx];
                    float vv[4] = {v.x, v.y, v.z, v.w};
                    int n_l = idx / 55;
                    int l0  = (idx - n_l * 55) * 4;
                    #pragma unroll
                    for (int jj = 0; jj < 4; jj++) {
                        int l  = l0 + jj;
                        int r  = l / 10, cc = l - r * 10;
                        int p1 = r / 11, h = r - p1 * 11;
                        int p2 = cc / 5, w = cc - p2 * 5;
                        int row = n_l * 4 + p1 * 2 + p2;
                        int d   = h * 5 + w;
                        float val = vv[jj];
                        *(float*)(sm + OFF_XP + (row * 60 + d) * 4) = val;
                        __half hh = __float2half_rn(val);
                        __half hl = __float2half_rn(val - __half2float(hh));
                        *(__half*)(sm + OFF_A + row * 272 + d * 2)        = hh;
                        *(__half*)(sm + OFF_A + row * 272 + (56 + d) * 2) = hl;
                    }
                }
            }
        }
        __syncthreads();

        // ======== Stage B: MMA (14 n-tiles as 7 pairs, 7+4 k-steps), stage D ========
        {
            uint32_t aF[7][4];
            #pragma unroll
            for (int ks = 0; ks < 7; ks++) ldsm4(aF[ks], aAddrBase + ks * 32);

            const int gid = lane >> 2, tig = lane & 3;
            #pragma unroll
            for (int ntp = 0; ntp < 7; ntp++) {
                float acc0[4] = {0.f, 0.f, 0.f, 0.f};
                float acc1[4] = {0.f, 0.f, 0.f, 0.f};
                uint32_t bbase = sb + OFF_B + (uint32_t)(ntp * 16 + jb) * 368 + kadd;
                #pragma unroll
                for (int ks = 0; ks < 7; ks++) {           // A[xh|xl] x B[wh|wh]
                    uint32_t bf[4];
                    ldsm4(bf, bbase + ks * 32);
                    mma16816(acc0, aF[ks], bf[0], bf[1]);
                    mma16816(acc1, aF[ks], bf[2], bf[3]);
                }
                #pragma unroll
                for (int ks = 0; ks < 4; ks++) {           // A[xh(+xl x 0)] x B[wl|0]
                    uint32_t bf[4];
                    ldsm4(bf, bbase + 224 + ks * 32);
                    mma16816(acc0, aF[ks], bf[0], bf[1]);
                    mma16816(acc1, aF[ks], bf[2], bf[3]);
                }
                int row = R0 + gid;
                int c0  = ntp * 16 + 2 * tig;
                *(float2*)(DS + row * 116 + c0)           = make_float2(acc0[0], acc0[1]);
                *(float2*)(DS + (row + 8) * 116 + c0)     = make_float2(acc0[2], acc0[3]);
                *(float2*)(DS + row * 116 + c0 + 8)       = make_float2(acc1[0], acc1[1]);
                *(float2*)(DS + (row + 8) * 116 + c0 + 8) = make_float2(acc1[2], acc1[3]);
            }
        }
        __syncthreads();

        // ======== Stage C: S = T x^T, softmax (all 8 warps) ========
        {
            int nl = tid >> 3;
            int s4 = (tid >> 1) & 3;
            int tp = tid & 1;
            const float4* tr = (const float4*)(DS + (nl * 4 + s4) * 116);
            const float4* x0 = (const float4*)(XP + (nl * 4 + 2 * tp) * 60);
            const float4* x1 = (const float4*)(XP + (nl * 4 + 2 * tp + 1) * 60);
            float sv0 = 0.f, sv1 = 0.f;
            #pragma unroll
            for (int i = 0; i < 14; i++) {
                float4 tv = tr[i], a = x0[i], b = x1[i];
                sv0 += tv.x * a.x + tv.y * a.y + tv.z * a.z + tv.w * a.w;
                sv1 += tv.x * b.x + tv.y * b.y + tv.z * b.z + tv.w * b.w;
            }
            float o0 = __shfl_xor_sync(0xffffffffu, sv0, 1);
            float o1 = __shfl_xor_sync(0xffffffffu, sv1, 1);
            float t0, t1, t2, t3;
            if (tp == 0) { t0 = sv0; t1 = sv1; t2 = o0; t3 = o1; }
            else         { t0 = o0;  t1 = o1;  t2 = sv0; t3 = sv1; }
            float m = fmaxf(fmaxf(t0, t1), fmaxf(t2, t3));
            float e0 = __expf(t0 - m), e1 = __expf(t1 - m);
            float e2 = __expf(t2 - m), e3 = __expf(t3 - m);
            float inv = 1.f / (e0 + e1 + e2 + e3);
            if (tp == 0)
                *(float4*)(sm + OFF_AT + (nl * 4 + s4) * 16) =
                    make_float4(e0 * inv, e1 * inv, e2 * inv, e3 * inv);
        }
        __syncthreads();

        // ======== Stage D: out = b + attn * U, stage patch-linear ========
        {
            int nl = tid >> 3;
            int s4 = (tid >> 1) & 3;
            int dh = tid & 1;
            int d0 = dh * 28;
            float4 at = *(const float4*)(sm + OFF_AT + (nl * 4 + s4) * 16);
            float av[4] = {at.x, at.y, at.z, at.w};
            float acc[28];
            {
                const float4* bb = (const float4*)(SB + d0);
                #pragma unroll
                for (int i = 0; i < 7; i++) {
                    float4 b = bb[i];
                    acc[4*i] = b.x; acc[4*i+1] = b.y; acc[4*i+2] = b.z; acc[4*i+3] = b.w;
                }
            }
            #pragma unroll
            for (int tt = 0; tt < 4; tt++) {
                const float4* ur = (const float4*)(DS + (nl * 4 + tt) * 116 + 56 + d0);
                float a = av[tt];
                #pragma unroll
                for (int i = 0; i < 7; i++) {
                    float4 u = ur[i];
                    acc[4*i]   += a * u.x; acc[4*i+1] += a * u.y;
                    acc[4*i+2] += a * u.z; acc[4*i+3] += a * u.w;
                }
            }
            float* os = (float*)(sm + OFF_OS) + nl * 224;
            int base = (s4 >> 1) * 110 + (s4 & 1) * 5;
            #pragma unroll
            for (int dd = 0; dd < 28; dd++) {
                int d = d0 + dd;
                if (d < 55) {
                    int h = d / 5, w = d - (d / 5) * 5;
                    os[base + h * 10 + w] = acc[dd];
                }
            }
        }
        __syncthreads();

        // ======== store: coalesced OS -> gmem ========
        {
            float* gout = out + (size_t)t * 7040;
            const float* os = (const float*)(sm + OFF_OS);
            #pragma unroll
            for (int i = 0; i < 7; i++) {
                int idx = tid + 256 * i;
                if (idx < 1760) {
                    int n = idx / 55, jj = idx - n * 55;
                    *(float4*)(gout + n * 220 + jj * 4) =
                        *(const float4*)(os + n * 224 + jj * 4);
                }
            }
        }
    }
}

extern "C" void kernel_launch(void* const* d_in, const int* in_sizes, int n_in,
                              void* d_out, int out_size) {
    const float* x   = (const float*)d_in[0];
    const float* wq  = (const float*)d_in[1];
    const float* wk  = (const float*)d_in[2];
    const float* wv  = (const float*)d_in[3];
    const float* wfc = (const float*)d_in[4];
    const float* bfc = (const float*)d_in[5];
    float* out = (float*)d_out;

    int nsm = 148;
    cudaDeviceGetAttribute(&nsm, cudaDevAttrMultiProcessorCount, 0);

    cudaFuncSetAttribute(mha_kernel, cudaFuncAttributeMaxDynamicSharedMemorySize, SMEM_TOTAL);
    prep_kernel<<<(112 * 184 + 255) / 256, 256>>>(wq, wk, wv, wfc);
    mha_kernel<<<nsm, 256, SMEM_TOTAL>>>(x, bfc, out);
}